// round 1
// baseline (speedup 1.0000x reference)
#include <cuda_runtime.h>
#include <cstdint>

// LinearTPReadOut: out[n] = w_tp/sqrt(3) * (1/128) * sum_i A_i(n)*B_i(n)
//   A_i(n) = sum_u x[n, 128 + 3u + i] * w_lin[u,0]
//   B_i(n) = sum_u x[n, 128 + 3u + i] * w_lin[u,1]
// x: (N, 1152) f32, w_lin: (128, 2) f32, w_tp: (1,) f32, out: (N,) f32
//
// One warp per row. Lane l handles u in [4l, 4l+4): 12 consecutive floats
// starting at column 128 + 12l (byte offset 512 + 48l -> 16B aligned since
// row stride = 4608 B). Three float4 loads per lane, fully coalesced.

#define ROW_STRIDE 1152
#define COL_OFF    128

__global__ __launch_bounds__(256)
void lintp_kernel(const float* __restrict__ x,
                  const float* __restrict__ w_lin,
                  const float* __restrict__ w_tp,
                  float* __restrict__ out, int n)
{
    const int warp = (blockIdx.x * blockDim.x + threadIdx.x) >> 5;
    const int lane = threadIdx.x & 31;
    if (warp >= n) return;

    // Weights for u = 4l .. 4l+3: w_lin is row-major (128,2), so
    // w_lin + 8*l covers [w0[4l],w1[4l],w0[4l+1],w1[4l+1], w0[4l+2],...]
    const float4* wp = reinterpret_cast<const float4*>(w_lin) + 2 * lane;
    const float4 wA = __ldg(wp);      // w0[4l], w1[4l], w0[4l+1], w1[4l+1]
    const float4 wB = __ldg(wp + 1);  // w0[4l+2], w1[4l+2], w0[4l+3], w1[4l+3]

    const float4* xp = reinterpret_cast<const float4*>(
        x + (size_t)warp * ROW_STRIDE + COL_OFF + 12 * lane);
    const float4 v0 = xp[0];
    const float4 v1 = xp[1];
    const float4 v2 = xp[2];

    // index map (12 floats = 4 u-groups of 3):
    //  v0 = {u0i0, u0i1, u0i2, u1i0}
    //  v1 = {u1i1, u1i2, u2i0, u2i1}
    //  v2 = {u2i2, u3i0, u3i1, u3i2}
    float A0 = v0.x*wA.x + v0.w*wA.z + v1.z*wB.x + v2.y*wB.z;
    float A1 = v0.y*wA.x + v1.x*wA.z + v1.w*wB.x + v2.z*wB.z;
    float A2 = v0.z*wA.x + v1.y*wA.z + v2.x*wB.x + v2.w*wB.z;
    float B0 = v0.x*wA.y + v0.w*wA.w + v1.z*wB.y + v2.y*wB.w;
    float B1 = v0.y*wA.y + v1.x*wA.w + v1.w*wB.y + v2.z*wB.w;
    float B2 = v0.z*wA.y + v1.y*wA.w + v2.x*wB.y + v2.w*wB.w;

    #pragma unroll
    for (int off = 16; off > 0; off >>= 1) {
        A0 += __shfl_down_sync(0xffffffffu, A0, off);
        A1 += __shfl_down_sync(0xffffffffu, A1, off);
        A2 += __shfl_down_sync(0xffffffffu, A2, off);
        B0 += __shfl_down_sync(0xffffffffu, B0, off);
        B1 += __shfl_down_sync(0xffffffffu, B1, off);
        B2 += __shfl_down_sync(0xffffffffu, B2, off);
    }

    if (lane == 0) {
        // scale = w_tp[0] * (1/sqrt(3)) * (1/sqrt(128))^2
        const float scale = __ldg(w_tp) * 0.57735026918962576451f * (1.0f / 128.0f);
        out[warp] = scale * (A0 * B0 + A1 * B1 + A2 * B2);
    }
}

extern "C" void kernel_launch(void* const* d_in, const int* in_sizes, int n_in,
                              void* d_out, int out_size)
{
    const float* x     = (const float*)d_in[0];
    const float* w_lin = (const float*)d_in[1];
    const float* w_tp  = (const float*)d_in[2];
    float* out = (float*)d_out;

    const int n = in_sizes[0] / ROW_STRIDE;  // 200000
    const int threads = 256;                 // 8 warps/block -> 8 rows/block
    const int blocks = (n + 7) / 8;
    lintp_kernel<<<blocks, threads>>>(x, w_lin, w_tp, out, n);
}